// round 13
// baseline (speedup 1.0000x reference)
#include <cuda_runtime.h>
#include <cuda_bf16.h>
#include <cstdint>

#define BATCH 8
#define NPTS 2048
#define CIN 128
#define DQK 32
#define NSEG 8
#define VROWS 144   // 128 v channels + civ row (128) + 15 zero pad rows
#define BN (BATCH * NPTS)

// ---------------- scratch (device globals) ----------------
__device__ __nv_bfloat16 g_qh[BN * DQK];
__device__ __nv_bfloat16 g_kh[BN * DQK];
__device__ __nv_bfloat16 g_vTh[(size_t)BATCH * VROWS * NPTS];  // [b][c][m]
__device__ __nv_bfloat16 g_wh[192 * CIN], g_wl[192 * CIN];     // Wq|Wk|Wv hi/lo
__device__ __nv_bfloat16 g_wph[CIN * CIN], g_wpl[CIN * CIN];   // Wp hi/lo
__device__ float g_xr[BN * CIN];
__device__ float g_psum[BN * NSEG];

// ---------------- helpers ----------------
__device__ __forceinline__ uint32_t smem_u32(const void* p) {
    uint32_t a;
    asm("{ .reg .u64 t; cvta.to.shared.u64 t, %1; cvt.u32.u64 %0, t; }" : "=r"(a) : "l"(p));
    return a;
}
__device__ __forceinline__ void ldsm_x4(uint32_t* r, uint32_t addr) {
    asm volatile("ldmatrix.sync.aligned.m8n8.x4.shared.b16 {%0,%1,%2,%3}, [%4];"
                 : "=r"(r[0]), "=r"(r[1]), "=r"(r[2]), "=r"(r[3]) : "r"(addr));
}
__device__ __forceinline__ void mma16816(float* c, const uint32_t* a, uint32_t b0, uint32_t b1) {
    asm volatile(
        "mma.sync.aligned.m16n8k16.row.col.f32.bf16.bf16.f32 "
        "{%0,%1,%2,%3}, {%4,%5,%6,%7}, {%8,%9}, {%0,%1,%2,%3};"
        : "+f"(c[0]), "+f"(c[1]), "+f"(c[2]), "+f"(c[3])
        : "r"(a[0]), "r"(a[1]), "r"(a[2]), "r"(a[3]), "r"(b0), "r"(b1));
}
__device__ __forceinline__ uint32_t bf2u(float a, float b) {
    __nv_bfloat162 h = __nv_bfloat162(__float2bfloat16(a), __float2bfloat16(b));
    return *(uint32_t*)&h;
}

// ---------------- K0: weights -> bf16 hi/lo, plus vT zero pad rows 129..143 ----------------
#define WN (192 * CIN + CIN * CIN)          // 40960 weight elements
__global__ __launch_bounds__(256) void k_prep(const float* __restrict__ Wq,
                                              const float* __restrict__ Wk,
                                              const float* __restrict__ Wv,
                                              const float* __restrict__ Wp) {
    int idx = blockIdx.x * 256 + threadIdx.x;
    if (idx < 192 * CIN) {
        int row = idx >> 7, col = idx & 127;
        float v;
        if (row < 32)      v = Wq[row * CIN + col];
        else if (row < 64) v = Wk[(row - 32) * CIN + col];
        else               v = Wv[(row - 64) * CIN + col];
        __nv_bfloat16 h = __float2bfloat16(v);
        g_wh[idx] = h;
        g_wl[idx] = __float2bfloat16(v - __bfloat162float(h));
    } else if (idx < WN) {
        int i2 = idx - 192 * CIN;
        float v = Wp[i2];
        __nv_bfloat16 h = __float2bfloat16(v);
        g_wph[i2] = h;
        g_wpl[i2] = __float2bfloat16(v - __bfloat162float(h));
    } else {
        int r = idx - WN;                    // over BATCH * 15 * NPTS (rows 129..143)
        int b = r / (15 * NPTS);
        int q = r - b * 15 * NPTS;
        int c = 129 + q / NPTS;
        int m = q & (NPTS - 1);
        g_vTh[((size_t)b * VROWS + c) * NPTS + m] = __float2bfloat16(0.0f);
    }
}

// ---------------- K1: q,k,v via 3-term hi/lo mma (fp32-accurate) ----------------
#define TS 72
__global__ __launch_bounds__(256) void k_qkv_mma(const float* __restrict__ x) {
    __shared__ __nv_bfloat16 Xh[64 * TS], Xl[64 * TS], Wh[64 * TS], Wl[64 * TS];
    const int tid = threadIdx.x, w = tid >> 5, l = tid & 31;
    const int r0 = blockIdx.x * 64;
    const int c0 = blockIdx.y * 64;       // [0,192): q 0-31, k 32-63, v 64-191
    const int wn = w & 3, wc = w >> 2;

    float acc[4][4] = {};
    for (int kc = 0; kc < CIN; kc += 64) {
        __syncthreads();
#pragma unroll
        for (int i = tid; i < 2048; i += 256) {
            int row = i >> 5, cp = i & 31;
            float2 v = *(const float2*)&x[(size_t)(r0 + row) * CIN + kc + cp * 2];
            __nv_bfloat16 h0 = __float2bfloat16(v.x), h1 = __float2bfloat16(v.y);
            Xh[row * TS + cp * 2] = h0;
            Xh[row * TS + cp * 2 + 1] = h1;
            Xl[row * TS + cp * 2] = __float2bfloat16(v.x - __bfloat162float(h0));
            Xl[row * TS + cp * 2 + 1] = __float2bfloat16(v.y - __bfloat162float(h1));
            *(uint32_t*)&Wh[row * TS + cp * 2] = *(const uint32_t*)&g_wh[(c0 + row) * CIN + kc + cp * 2];
            *(uint32_t*)&Wl[row * TS + cp * 2] = *(const uint32_t*)&g_wl[(c0 + row) * CIN + kc + cp * 2];
        }
        __syncthreads();
        const uint32_t xh = smem_u32(Xh), xl = smem_u32(Xl);
        const uint32_t wh = smem_u32(Wh), wl = smem_u32(Wl);
#pragma unroll
        for (int kp = 0; kp < 2; kp++) {
            uint32_t ah[2][4], al[2][4];
            ldsm_x4(ah[0], xh + (16 * wn + (l & 15)) * (TS * 2) + kp * 64 + (l >> 4) * 16);
            ldsm_x4(ah[1], xh + (16 * wn + (l & 15)) * (TS * 2) + kp * 64 + 32 + (l >> 4) * 16);
            ldsm_x4(al[0], xl + (16 * wn + (l & 15)) * (TS * 2) + kp * 64 + (l >> 4) * 16);
            ldsm_x4(al[1], xl + (16 * wn + (l & 15)) * (TS * 2) + kp * 64 + 32 + (l >> 4) * 16);
#pragma unroll
            for (int j = 0; j < 4; j++) {
                uint32_t bh[4], bl[4];
                uint32_t boff = (32 * wc + 8 * j + (l & 7)) * (TS * 2) + kp * 64 +
                                ((l >> 3) & 1) * 16 + (l >> 4) * 32;
                ldsm_x4(bh, wh + boff);
                ldsm_x4(bl, wl + boff);
                mma16816(acc[j], ah[0], bh[0], bh[1]);
                mma16816(acc[j], ah[1], bh[2], bh[3]);
                mma16816(acc[j], ah[0], bl[0], bl[1]);
                mma16816(acc[j], ah[1], bl[2], bl[3]);
                mma16816(acc[j], al[0], bh[0], bh[1]);
                mma16816(acc[j], al[1], bh[2], bh[3]);
            }
        }
    }

    const int g = l >> 2, tig = l & 3;
#pragma unroll
    for (int j = 0; j < 4; j++) {
        int col = c0 + 32 * wc + 8 * j + 2 * tig;
#pragma unroll
        for (int h = 0; h < 2; h++) {
            int r = r0 + 16 * wn + g + h * 8;
            int b = r >> 11, n = r & (NPTS - 1);
            float v0 = acc[j][h * 2], v1 = acc[j][h * 2 + 1];
            if (col < 32) {
                *(uint32_t*)&g_qh[(size_t)(b * NPTS + n) * DQK + col] = bf2u(v0, v1);
            } else if (col < 64) {
                *(uint32_t*)&g_kh[(size_t)(b * NPTS + n) * DQK + col - 32] = bf2u(v0, v1);
            } else {
                int c = col - 64;
                g_vTh[((size_t)b * VROWS + c) * NPTS + n] = __float2bfloat16(v0);
                g_vTh[((size_t)b * VROWS + c + 1) * NPTS + n] = __float2bfloat16(v1);
            }
        }
    }
}

// ---------------- K2: column sums of exp(E) via transposed E ----------------
#define QKS 40
__global__ __launch_bounds__(256) void k_stats() {
    __shared__ __nv_bfloat16 Ks[128 * QKS];
    __shared__ __nv_bfloat16 Qs[128 * QKS];
    const int tid = threadIdx.x, w = tid >> 5, l = tid & 31;
    const int b = blockIdx.z, m0 = blockIdx.x * 128, seg = blockIdx.y;

#pragma unroll
    for (int i = tid; i < 512; i += 256) {
        int row = i >> 2, jj = i & 3;
        *(uint4*)&Ks[row * QKS + jj * 8] =
            *(const uint4*)&g_kh[(size_t)(b * NPTS + m0 + row) * DQK + jj * 8];
    }
    __syncthreads();

    const uint32_t kb = smem_u32(Ks), qb = smem_u32(Qs);
    uint32_t a[2][4];       // K fragments (constant across q-tiles)
    ldsm_x4(a[0], kb + (16 * w + (l & 15)) * (QKS * 2) + (l >> 4) * 16);
    ldsm_x4(a[1], kb + (16 * w + (l & 15)) * (QKS * 2) + 32 + (l >> 4) * 16);

    float sum0 = 0.f, sum1 = 0.f;
#pragma unroll
    for (int t = 0; t < 2; t++) {
        const int q0 = (seg * 2 + t) * 128;
        __syncthreads();
#pragma unroll
        for (int i = tid; i < 512; i += 256) {
            int row = i >> 2, jj = i & 3;
            *(uint4*)&Qs[row * QKS + jj * 8] =
                *(const uint4*)&g_qh[(size_t)(b * NPTS + q0 + row) * DQK + jj * 8];
        }
        __syncthreads();
#pragma unroll
        for (int j = 0; j < 16; j++) {
            float acc[4] = {0.f, 0.f, 0.f, 0.f};
            uint32_t bb[4];
            ldsm_x4(bb, qb + (8 * j + (l & 7)) * (QKS * 2) + ((l >> 3) & 1) * 16 + (l >> 4) * 32);
            mma16816(acc, a[0], bb[0], bb[1]);
            mma16816(acc, a[1], bb[2], bb[3]);
            sum0 += __expf(acc[0]) + __expf(acc[1]);
            sum1 += __expf(acc[2]) + __expf(acc[3]);
        }
    }

    sum0 += __shfl_xor_sync(0xFFFFFFFFu, sum0, 1);
    sum0 += __shfl_xor_sync(0xFFFFFFFFu, sum0, 2);
    sum1 += __shfl_xor_sync(0xFFFFFFFFu, sum1, 1);
    sum1 += __shfl_xor_sync(0xFFFFFFFFu, sum1, 2);
    if ((l & 3) == 0) {
        int m = m0 + 16 * w + (l >> 2);
        g_psum[(b * NPTS + m) * NSEG + seg] = sum0;
        g_psum[(b * NPTS + m + 8) * NSEG + seg] = sum1;
    }
}

// ---------------- K3: fused civ computation + vT pre-scale; row 128 := civ ----------------
// Block: one batch x 256 keys. Stage 1: civ into smem. Stage 2: scale 129 vT rows.
__global__ __launch_bounds__(256) void k_vscale() {
    __shared__ float civ[256];
    const int tid = threadIdx.x;
    const int b = blockIdx.x >> 3;
    const int m0 = (blockIdx.x & 7) * 256;

    {   // stage 1: civ[m] = 1 / sum(psum[m][0..7])
        const float* ps = &g_psum[(size_t)(b * NPTS + m0 + tid) * NSEG];
        float s = ps[0] + ps[1] + ps[2] + ps[3] + ps[4] + ps[5] + ps[6] + ps[7];
        civ[tid] = 1.0f / s;
    }
    __syncthreads();

    // stage 2: 129 rows x 32 uint4-groups (8 bf16 each)
    for (int i = tid; i < 129 * 32; i += 256) {
        int c = i >> 5;
        int m8 = (i & 31) * 8;
        __nv_bfloat16* dst = &g_vTh[((size_t)b * VROWS + c) * NPTS + m0 + m8];
        uint4 out;
        __nv_bfloat16* o = (__nv_bfloat16*)&out;
        if (c < 128) {
            uint4 raw = *(uint4*)dst;
            __nv_bfloat16* v = (__nv_bfloat16*)&raw;
#pragma unroll
            for (int k = 0; k < 8; k++)
                o[k] = __float2bfloat16(__bfloat162float(v[k]) * civ[m8 + k]);
        } else {   // c == 128: civ row (replaces ones column)
#pragma unroll
            for (int k = 0; k < 8; k++) o[k] = __float2bfloat16(civ[m8 + k]);
        }
        *(uint4*)dst = out;
    }
}

// ---------------- K4: x_r — recompute E, p = exp(e) direct (civ folded into vT) ----------
// Block: 64 query rows; 8 warps = 4 row-groups x 2 col-halves (72 cols each).
#define VSS 72
__global__ __launch_bounds__(256, 2) void k_xr_mma() {
    __shared__ __nv_bfloat16 Qs[64 * QKS];
    __shared__ __nv_bfloat16 Kc[64 * QKS];
    __shared__ __nv_bfloat16 Vts[VROWS * VSS];
    __shared__ float rsum[64];
    const int tid = threadIdx.x, w = tid >> 5, l = tid & 31;
    const int b = blockIdx.y, n0 = blockIdx.x * 64;
    const int g = l >> 2, tig = l & 3;
    const int wn = w & 3, wc = w >> 2;

    {
        int row = tid >> 2, jj = tid & 3;   // exactly 256 uint4
        *(uint4*)&Qs[row * QKS + jj * 8] =
            *(const uint4*)&g_qh[(size_t)(b * NPTS + n0 + row) * DQK + jj * 8];
    }
    const uint32_t qb = smem_u32(Qs), kb = smem_u32(Kc), vb = smem_u32(Vts);

    float acc2[9][4];
#pragma unroll
    for (int j = 0; j < 9; j++)
#pragma unroll
        for (int q = 0; q < 4; q++) acc2[j][q] = 0.f;

    __syncthreads();
    uint32_t a[2][4];   // Q fragments constant across chunks
    ldsm_x4(a[0], qb + (16 * wn + (l & 15)) * (QKS * 2) + (l >> 4) * 16);
    ldsm_x4(a[1], qb + (16 * wn + (l & 15)) * (QKS * 2) + 32 + (l >> 4) * 16);

    for (int mc = 0; mc < NPTS; mc += 64) {
        __syncthreads();
        {
            int row = tid >> 2, jj = tid & 3;
            *(uint4*)&Kc[row * QKS + jj * 8] =
                *(const uint4*)&g_kh[(size_t)(b * NPTS + mc + row) * DQK + jj * 8];
        }
#pragma unroll
        for (int i = tid; i < 1152; i += 256) {
            int row = i >> 3, jj = i & 7;
            *(uint4*)&Vts[row * VSS + jj * 8] =
                *(const uint4*)&g_vTh[((size_t)b * VROWS + row) * NPTS + mc + jj * 8];
        }
        __syncthreads();

#pragma unroll
        for (int half = 0; half < 2; half++) {
            // E for keys [mc+32*half, +32): 4 frags
            float ae[4][4];
#pragma unroll
            for (int j = 0; j < 4; j++)
#pragma unroll
                for (int q = 0; q < 4; q++) ae[j][q] = 0.f;
#pragma unroll
            for (int j = 0; j < 4; j++) {
                uint32_t bb[4];
                ldsm_x4(bb, kb + (8 * (4 * half + j) + (l & 7)) * (QKS * 2) +
                                ((l >> 3) & 1) * 16 + (l >> 4) * 32);
                mma16816(ae[j], a[0], bb[0], bb[1]);
                mma16816(ae[j], a[1], bb[2], bb[3]);
            }
            // p = exp(e) directly; civ is folded into vT
            uint32_t a2[2][4];
#pragma unroll
            for (int s = 0; s < 2; s++) {
                int j0 = 2 * s, j1 = 2 * s + 1;
                a2[s][0] = bf2u(__expf(ae[j0][0]), __expf(ae[j0][1]));
                a2[s][1] = bf2u(__expf(ae[j0][2]), __expf(ae[j0][3]));
                a2[s][2] = bf2u(__expf(ae[j1][0]), __expf(ae[j1][1]));
                a2[s][3] = bf2u(__expf(ae[j1][2]), __expf(ae[j1][3]));
            }
            // PV over this 32-key half: 9 col frags per warp
#pragma unroll
            for (int j2 = 0; j2 < 9; j2++) {
                uint32_t bb[4];
                ldsm_x4(bb, vb + (72 * wc + 8 * j2 + (l & 7)) * (VSS * 2) + half * 64 +
                                ((l >> 3) & 1) * 16 + (l >> 4) * 32);
                mma16816(acc2[j2], a2[0], bb[0], bb[1]);
                mma16816(acc2[j2], a2[1], bb[2], bb[3]);
            }
        }
    }
    __syncthreads();

    if (wc == 1 && tig == 0) {            // col 128 = civ column -> denominator
        rsum[16 * wn + g] = acc2[7][0];
        rsum[16 * wn + g + 8] = acc2[7][2];
    }
    __syncthreads();

    const int row = 16 * wn + g;
    const float inv0 = 1.0f / (1e-9f + rsum[row]);
    const float inv1 = 1.0f / (1e-9f + rsum[row + 8]);
    float* dst0 = &g_xr[((size_t)b * NPTS + n0 + row) * CIN];
    float* dst1 = &g_xr[((size_t)b * NPTS + n0 + row + 8) * CIN];
#pragma unroll
    for (int j2 = 0; j2 < 9; j2++) {
        int col = 72 * wc + 8 * j2 + 2 * tig;
        if (col < 128) {
            *(float2*)&dst0[col] = make_float2(acc2[j2][0] * inv0, acc2[j2][1] * inv0);
            *(float2*)&dst1[col] = make_float2(acc2[j2][2] * inv1, acc2[j2][3] * inv1);
        }
    }
}

// ---------------- K5: y = leaky(BN((x - xr) @ Wp^T)) + x via 3-term hi/lo mma ----------------
__global__ __launch_bounds__(256) void k_proj_mma(const float* __restrict__ x,
                                                  const float* __restrict__ gamma,
                                                  const float* __restrict__ beta,
                                                  const float* __restrict__ mean,
                                                  const float* __restrict__ var,
                                                  float* __restrict__ out) {
    __shared__ __nv_bfloat16 Dh[64 * TS], Dl[64 * TS], Wh[64 * TS], Wl[64 * TS];
    const int tid = threadIdx.x, w = tid >> 5, l = tid & 31;
    const int r0 = blockIdx.x * 64;
    const int c0 = blockIdx.y * 64;
    const int wn = w & 3, wc = w >> 2;

    float acc[4][4] = {};
    for (int kc = 0; kc < CIN; kc += 64) {
        __syncthreads();
#pragma unroll
        for (int i = tid; i < 2048; i += 256) {
            int row = i >> 5, cp = i & 31;
            float2 xv = *(const float2*)&x[(size_t)(r0 + row) * CIN + kc + cp * 2];
            float2 rv = *(const float2*)&g_xr[(size_t)(r0 + row) * CIN + kc + cp * 2];
            float d0 = xv.x - rv.x, d1 = xv.y - rv.y;
            __nv_bfloat16 h0 = __float2bfloat16(d0), h1 = __float2bfloat16(d1);
            Dh[row * TS + cp * 2] = h0;
            Dh[row * TS + cp * 2 + 1] = h1;
            Dl[row * TS + cp * 2] = __float2bfloat16(d0 - __bfloat162float(h0));
            Dl[row * TS + cp * 2 + 1] = __float2bfloat16(d1 - __bfloat162float(h1));
            *(uint32_t*)&Wh[row * TS + cp * 2] = *(const uint32_t*)&g_wph[(c0 + row) * CIN + kc + cp * 2];
            *(uint32_t*)&Wl[row * TS + cp * 2] = *(const uint32_t*)&g_wpl[(c0 + row) * CIN + kc + cp * 2];
        }
        __syncthreads();
        const uint32_t dh = smem_u32(Dh), dl = smem_u32(Dl);
        const uint32_t wh = smem_u32(Wh), wl = smem_u32(Wl);
#pragma unroll
        for (int kp = 0; kp < 2; kp++) {
            uint32_t ah[2][4], al[2][4];
            ldsm_x4(ah[0], dh + (16 * wn + (l & 15)) * (TS * 2) + kp * 64 + (l >> 4) * 16);
            ldsm_x4(ah[1], dh + (16 * wn + (l & 15)) * (TS * 2) + kp * 64 + 32 + (l >> 4) * 16);
            ldsm_x4(al[0], dl + (16 * wn + (l & 15)) * (TS * 2) + kp * 64 + (l >> 4) * 16);
            ldsm_x4(al[1], dl + (16 * wn + (l & 15)) * (TS * 2) + kp * 64 + 32 + (l >> 4) * 16);
#pragma unroll
            for (int j = 0; j < 4; j++) {
                uint32_t bh[4], bl[4];
                uint32_t boff = (32 * wc + 8 * j + (l & 7)) * (TS * 2) + kp * 64 +
                                ((l >> 3) & 1) * 16 + (l >> 4) * 32;
                ldsm_x4(bh, wh + boff);
                ldsm_x4(bl, wl + boff);
                mma16816(acc[j], ah[0], bh[0], bh[1]);
                mma16816(acc[j], ah[1], bh[2], bh[3]);
                mma16816(acc[j], ah[0], bl[0], bl[1]);
                mma16816(acc[j], ah[1], bl[2], bl[3]);
                mma16816(acc[j], al[0], bh[0], bh[1]);
                mma16816(acc[j], al[1], bh[2], bh[3]);
            }
        }
    }

    const int g = l >> 2, tig = l & 3;
#pragma unroll
    for (int j = 0; j < 4; j++) {
        int o = c0 + 32 * wc + 8 * j + 2 * tig;
        float sc0 = gamma[o] * rsqrtf(var[o] + 1e-5f);
        float sc1 = gamma[o + 1] * rsqrtf(var[o + 1] + 1e-5f);
        float b0 = beta[o], b1 = beta[o + 1];
        float m0 = mean[o], m1 = mean[o + 1];
#pragma unroll
        for (int h = 0; h < 2; h++) {
            int r = r0 + 16 * wn + g + h * 8;
            float2 xv = *(const float2*)&x[(size_t)r * CIN + o];
            float y0 = (acc[j][h * 2] - m0) * sc0 + b0;
            float y1 = (acc[j][h * 2 + 1] - m1) * sc1 + b1;
            y0 = (y0 >= 0.f) ? y0 : 0.01f * y0;
            y1 = (y1 >= 0.f) ? y1 : 0.01f * y1;
            *(float2*)&out[(size_t)r * CIN + o] = make_float2(y0 + xv.x, y1 + xv.y);
        }
    }
}

// ---------------- launch ----------------
extern "C" void kernel_launch(void* const* d_in, const int* in_sizes, int n_in,
                              void* d_out, int out_size) {
    const float* x     = (const float*)d_in[0];
    const float* Wq    = (const float*)d_in[1];
    const float* Wk    = (const float*)d_in[2];
    const float* Wv    = (const float*)d_in[3];
    const float* Wp    = (const float*)d_in[4];
    const float* gamma = (const float*)d_in[5];
    const float* beta  = (const float*)d_in[6];
    const float* mean  = (const float*)d_in[7];
    const float* var   = (const float*)d_in[8];
    float* out = (float*)d_out;

    k_prep<<<(WN + BATCH * 15 * NPTS + 255) / 256, 256>>>(Wq, Wk, Wv, Wp);
    k_qkv_mma<<<dim3((BATCH * NPTS) / 64, 3), 256>>>(x);
    k_stats<<<dim3(NPTS / 128, NSEG, BATCH), 256>>>();
    k_vscale<<<BATCH * 8, 256>>>();
    k_xr_mma<<<dim3(NPTS / 64, BATCH), 256>>>();
    k_proj_mma<<<dim3((BATCH * NPTS) / 64, 2), 256>>>(x, gamma, beta, mean, var, out);
}

// round 14
// speedup vs baseline: 1.0386x; 1.0386x over previous
#include <cuda_runtime.h>
#include <cuda_bf16.h>
#include <cstdint>

#define BATCH 8
#define NPTS 2048
#define CIN 128
#define DQK 32
#define NSEG 8
#define VROWS 144   // 128 v channels + civ row (128) + 15 zero pad rows
#define BN (BATCH * NPTS)

// ---------------- scratch (device globals) ----------------
__device__ __nv_bfloat16 g_qh[BN * DQK];
__device__ __nv_bfloat16 g_kh[BN * DQK];
__device__ __nv_bfloat16 g_vTh[(size_t)BATCH * VROWS * NPTS];  // [b][c][m]
__device__ __nv_bfloat16 g_wh[192 * CIN], g_wl[192 * CIN];     // Wq|Wk|Wv hi/lo
__device__ __nv_bfloat16 g_wph[CIN * CIN], g_wpl[CIN * CIN];   // Wp hi/lo
__device__ float g_xr[BN * CIN];
__device__ float g_psum[BN * NSEG];

// ---------------- helpers ----------------
__device__ __forceinline__ uint32_t smem_u32(const void* p) {
    uint32_t a;
    asm("{ .reg .u64 t; cvta.to.shared.u64 t, %1; cvt.u32.u64 %0, t; }" : "=r"(a) : "l"(p));
    return a;
}
__device__ __forceinline__ void ldsm_x4(uint32_t* r, uint32_t addr) {
    asm volatile("ldmatrix.sync.aligned.m8n8.x4.shared.b16 {%0,%1,%2,%3}, [%4];"
                 : "=r"(r[0]), "=r"(r[1]), "=r"(r[2]), "=r"(r[3]) : "r"(addr));
}
__device__ __forceinline__ void mma16816(float* c, const uint32_t* a, uint32_t b0, uint32_t b1) {
    asm volatile(
        "mma.sync.aligned.m16n8k16.row.col.f32.bf16.bf16.f32 "
        "{%0,%1,%2,%3}, {%4,%5,%6,%7}, {%8,%9}, {%0,%1,%2,%3};"
        : "+f"(c[0]), "+f"(c[1]), "+f"(c[2]), "+f"(c[3])
        : "r"(a[0]), "r"(a[1]), "r"(a[2]), "r"(a[3]), "r"(b0), "r"(b1));
}
__device__ __forceinline__ uint32_t bf2u(float a, float b) {
    __nv_bfloat162 h = __nv_bfloat162(__float2bfloat16(a), __float2bfloat16(b));
    return *(uint32_t*)&h;
}

// ---------------- K0: weights -> bf16 hi/lo, plus vT zero pad rows 129..143 ----------------
#define WN (192 * CIN + CIN * CIN)          // 40960 weight elements
__global__ __launch_bounds__(256) void k_prep(const float* __restrict__ Wq,
                                              const float* __restrict__ Wk,
                                              const float* __restrict__ Wv,
                                              const float* __restrict__ Wp) {
    int idx = blockIdx.x * 256 + threadIdx.x;
    if (idx < 192 * CIN) {
        int row = idx >> 7, col = idx & 127;
        float v;
        if (row < 32)      v = Wq[row * CIN + col];
        else if (row < 64) v = Wk[(row - 32) * CIN + col];
        else               v = Wv[(row - 64) * CIN + col];
        __nv_bfloat16 h = __float2bfloat16(v);
        g_wh[idx] = h;
        g_wl[idx] = __float2bfloat16(v - __bfloat162float(h));
    } else if (idx < WN) {
        int i2 = idx - 192 * CIN;
        float v = Wp[i2];
        __nv_bfloat16 h = __float2bfloat16(v);
        g_wph[i2] = h;
        g_wpl[i2] = __float2bfloat16(v - __bfloat162float(h));
    } else {
        int r = idx - WN;                    // over BATCH * 15 * NPTS (rows 129..143)
        int b = r / (15 * NPTS);
        int q = r - b * 15 * NPTS;
        int c = 129 + q / NPTS;
        int m = q & (NPTS - 1);
        g_vTh[((size_t)b * VROWS + c) * NPTS + m] = __float2bfloat16(0.0f);
    }
}

// ---------------- K1: q,k,v via 3-term hi/lo mma (fp32-accurate) ----------------
#define TS 72
__global__ __launch_bounds__(256) void k_qkv_mma(const float* __restrict__ x) {
    __shared__ __nv_bfloat16 Xh[64 * TS], Xl[64 * TS], Wh[64 * TS], Wl[64 * TS];
    const int tid = threadIdx.x, w = tid >> 5, l = tid & 31;
    const int r0 = blockIdx.x * 64;
    const int c0 = blockIdx.y * 64;       // [0,192): q 0-31, k 32-63, v 64-191
    const int wn = w & 3, wc = w >> 2;

    float acc[4][4] = {};
    for (int kc = 0; kc < CIN; kc += 64) {
        __syncthreads();
#pragma unroll
        for (int i = tid; i < 2048; i += 256) {
            int row = i >> 5, cp = i & 31;
            float2 v = *(const float2*)&x[(size_t)(r0 + row) * CIN + kc + cp * 2];
            __nv_bfloat16 h0 = __float2bfloat16(v.x), h1 = __float2bfloat16(v.y);
            Xh[row * TS + cp * 2] = h0;
            Xh[row * TS + cp * 2 + 1] = h1;
            Xl[row * TS + cp * 2] = __float2bfloat16(v.x - __bfloat162float(h0));
            Xl[row * TS + cp * 2 + 1] = __float2bfloat16(v.y - __bfloat162float(h1));
            *(uint32_t*)&Wh[row * TS + cp * 2] = *(const uint32_t*)&g_wh[(c0 + row) * CIN + kc + cp * 2];
            *(uint32_t*)&Wl[row * TS + cp * 2] = *(const uint32_t*)&g_wl[(c0 + row) * CIN + kc + cp * 2];
        }
        __syncthreads();
        const uint32_t xh = smem_u32(Xh), xl = smem_u32(Xl);
        const uint32_t wh = smem_u32(Wh), wl = smem_u32(Wl);
#pragma unroll
        for (int kp = 0; kp < 2; kp++) {
            uint32_t ah[2][4], al[2][4];
            ldsm_x4(ah[0], xh + (16 * wn + (l & 15)) * (TS * 2) + kp * 64 + (l >> 4) * 16);
            ldsm_x4(ah[1], xh + (16 * wn + (l & 15)) * (TS * 2) + kp * 64 + 32 + (l >> 4) * 16);
            ldsm_x4(al[0], xl + (16 * wn + (l & 15)) * (TS * 2) + kp * 64 + (l >> 4) * 16);
            ldsm_x4(al[1], xl + (16 * wn + (l & 15)) * (TS * 2) + kp * 64 + 32 + (l >> 4) * 16);
#pragma unroll
            for (int j = 0; j < 4; j++) {
                uint32_t bh[4], bl[4];
                uint32_t boff = (32 * wc + 8 * j + (l & 7)) * (TS * 2) + kp * 64 +
                                ((l >> 3) & 1) * 16 + (l >> 4) * 32;
                ldsm_x4(bh, wh + boff);
                ldsm_x4(bl, wl + boff);
                mma16816(acc[j], ah[0], bh[0], bh[1]);
                mma16816(acc[j], ah[1], bh[2], bh[3]);
                mma16816(acc[j], ah[0], bl[0], bl[1]);
                mma16816(acc[j], ah[1], bl[2], bl[3]);
                mma16816(acc[j], al[0], bh[0], bh[1]);
                mma16816(acc[j], al[1], bh[2], bh[3]);
            }
        }
    }

    const int g = l >> 2, tig = l & 3;
#pragma unroll
    for (int j = 0; j < 4; j++) {
        int col = c0 + 32 * wc + 8 * j + 2 * tig;
#pragma unroll
        for (int h = 0; h < 2; h++) {
            int r = r0 + 16 * wn + g + h * 8;
            int b = r >> 11, n = r & (NPTS - 1);
            float v0 = acc[j][h * 2], v1 = acc[j][h * 2 + 1];
            if (col < 32) {
                *(uint32_t*)&g_qh[(size_t)(b * NPTS + n) * DQK + col] = bf2u(v0, v1);
            } else if (col < 64) {
                *(uint32_t*)&g_kh[(size_t)(b * NPTS + n) * DQK + col - 32] = bf2u(v0, v1);
            } else {
                int c = col - 64;
                g_vTh[((size_t)b * VROWS + c) * NPTS + n] = __float2bfloat16(v0);
                g_vTh[((size_t)b * VROWS + c + 1) * NPTS + n] = __float2bfloat16(v1);
            }
        }
    }
}

// ---------------- K2: column sums of exp(E) via transposed E ----------------
#define QKS 40
__global__ __launch_bounds__(256) void k_stats() {
    __shared__ __nv_bfloat16 Ks[128 * QKS];
    __shared__ __nv_bfloat16 Qs[128 * QKS];
    const int tid = threadIdx.x, w = tid >> 5, l = tid & 31;
    const int b = blockIdx.z, m0 = blockIdx.x * 128, seg = blockIdx.y;

#pragma unroll
    for (int i = tid; i < 512; i += 256) {
        int row = i >> 2, jj = i & 3;
        *(uint4*)&Ks[row * QKS + jj * 8] =
            *(const uint4*)&g_kh[(size_t)(b * NPTS + m0 + row) * DQK + jj * 8];
    }
    __syncthreads();

    const uint32_t kb = smem_u32(Ks), qb = smem_u32(Qs);
    uint32_t a[2][4];       // K fragments (constant across q-tiles)
    ldsm_x4(a[0], kb + (16 * w + (l & 15)) * (QKS * 2) + (l >> 4) * 16);
    ldsm_x4(a[1], kb + (16 * w + (l & 15)) * (QKS * 2) + 32 + (l >> 4) * 16);

    float sum0 = 0.f, sum1 = 0.f;
#pragma unroll
    for (int t = 0; t < 2; t++) {
        const int q0 = (seg * 2 + t) * 128;
        __syncthreads();
#pragma unroll
        for (int i = tid; i < 512; i += 256) {
            int row = i >> 2, jj = i & 3;
            *(uint4*)&Qs[row * QKS + jj * 8] =
                *(const uint4*)&g_qh[(size_t)(b * NPTS + q0 + row) * DQK + jj * 8];
        }
        __syncthreads();
#pragma unroll
        for (int j = 0; j < 16; j++) {
            float acc[4] = {0.f, 0.f, 0.f, 0.f};
            uint32_t bb[4];
            ldsm_x4(bb, qb + (8 * j + (l & 7)) * (QKS * 2) + ((l >> 3) & 1) * 16 + (l >> 4) * 32);
            mma16816(acc, a[0], bb[0], bb[1]);
            mma16816(acc, a[1], bb[2], bb[3]);
            sum0 += __expf(acc[0]) + __expf(acc[1]);
            sum1 += __expf(acc[2]) + __expf(acc[3]);
        }
    }

    sum0 += __shfl_xor_sync(0xFFFFFFFFu, sum0, 1);
    sum0 += __shfl_xor_sync(0xFFFFFFFFu, sum0, 2);
    sum1 += __shfl_xor_sync(0xFFFFFFFFu, sum1, 1);
    sum1 += __shfl_xor_sync(0xFFFFFFFFu, sum1, 2);
    if ((l & 3) == 0) {
        int m = m0 + 16 * w + (l >> 2);
        g_psum[(b * NPTS + m) * NSEG + seg] = sum0;
        g_psum[(b * NPTS + m + 8) * NSEG + seg] = sum1;
    }
}

// ---------------- K3: fused civ + vT pre-scale, parallel over 8 row-groups ----------------
// Block: (key-range kx, batch b, row-group rg). Stage 1: civ for 256 keys (recomputed
// per row-group; 2KB L2-hot). Stage 2: scale 16 vT rows (rg 7 also does civ row 128).
__global__ __launch_bounds__(256) void k_vscale() {
    __shared__ float civ[256];
    const int tid = threadIdx.x;
    const int m0 = blockIdx.x * 256;
    const int b = blockIdx.y;
    const int rg = blockIdx.z;

    {   // stage 1: civ[m] = 1 / sum(psum[m][0..7])
        const float* ps = &g_psum[(size_t)(b * NPTS + m0 + tid) * NSEG];
        float s = ps[0] + ps[1] + ps[2] + ps[3] + ps[4] + ps[5] + ps[6] + ps[7];
        civ[tid] = 1.0f / s;
    }
    __syncthreads();

    // stage 2: rows [16*rg, 16*rg+16), each 32 uint4-groups; rg==7 adds row 128
    const int nrows = (rg == 7) ? 17 : 16;
#pragma unroll 2
    for (int i = tid; i < nrows * 32; i += 256) {
        int cr = i >> 5;
        int c = (cr == 16) ? 128 : (rg * 16 + cr);
        int m8 = (i & 31) * 8;
        __nv_bfloat16* dst = &g_vTh[((size_t)b * VROWS + c) * NPTS + m0 + m8];
        uint4 out;
        __nv_bfloat16* o = (__nv_bfloat16*)&out;
        if (c < 128) {
            uint4 raw = *(uint4*)dst;
            __nv_bfloat16* v = (__nv_bfloat16*)&raw;
#pragma unroll
            for (int k = 0; k < 8; k++)
                o[k] = __float2bfloat16(__bfloat162float(v[k]) * civ[m8 + k]);
        } else {   // civ row (replaces ones column)
#pragma unroll
            for (int k = 0; k < 8; k++) o[k] = __float2bfloat16(civ[m8 + k]);
        }
        *(uint4*)dst = out;
    }
}

// ---------------- K4: x_r — recompute E, p = exp(e) direct (civ folded into vT) ----------
// Block: 64 query rows; 8 warps = 4 row-groups x 2 col-halves (72 cols each).
#define VSS 72
__global__ __launch_bounds__(256, 2) void k_xr_mma() {
    __shared__ __nv_bfloat16 Qs[64 * QKS];
    __shared__ __nv_bfloat16 Kc[64 * QKS];
    __shared__ __nv_bfloat16 Vts[VROWS * VSS];
    __shared__ float rsum[64];
    const int tid = threadIdx.x, w = tid >> 5, l = tid & 31;
    const int b = blockIdx.y, n0 = blockIdx.x * 64;
    const int g = l >> 2, tig = l & 3;
    const int wn = w & 3, wc = w >> 2;

    {
        int row = tid >> 2, jj = tid & 3;   // exactly 256 uint4
        *(uint4*)&Qs[row * QKS + jj * 8] =
            *(const uint4*)&g_qh[(size_t)(b * NPTS + n0 + row) * DQK + jj * 8];
    }
    const uint32_t qb = smem_u32(Qs), kb = smem_u32(Kc), vb = smem_u32(Vts);

    float acc2[9][4];
#pragma unroll
    for (int j = 0; j < 9; j++)
#pragma unroll
        for (int q = 0; q < 4; q++) acc2[j][q] = 0.f;

    __syncthreads();
    uint32_t a[2][4];   // Q fragments constant across chunks
    ldsm_x4(a[0], qb + (16 * wn + (l & 15)) * (QKS * 2) + (l >> 4) * 16);
    ldsm_x4(a[1], qb + (16 * wn + (l & 15)) * (QKS * 2) + 32 + (l >> 4) * 16);

    for (int mc = 0; mc < NPTS; mc += 64) {
        __syncthreads();
        {
            int row = tid >> 2, jj = tid & 3;
            *(uint4*)&Kc[row * QKS + jj * 8] =
                *(const uint4*)&g_kh[(size_t)(b * NPTS + mc + row) * DQK + jj * 8];
        }
#pragma unroll
        for (int i = tid; i < 1152; i += 256) {
            int row = i >> 3, jj = i & 7;
            *(uint4*)&Vts[row * VSS + jj * 8] =
                *(const uint4*)&g_vTh[((size_t)b * VROWS + row) * NPTS + mc + jj * 8];
        }
        __syncthreads();

#pragma unroll
        for (int half = 0; half < 2; half++) {
            // E for keys [mc+32*half, +32): 4 frags
            float ae[4][4];
#pragma unroll
            for (int j = 0; j < 4; j++)
#pragma unroll
                for (int q = 0; q < 4; q++) ae[j][q] = 0.f;
#pragma unroll
            for (int j = 0; j < 4; j++) {
                uint32_t bb[4];
                ldsm_x4(bb, kb + (8 * (4 * half + j) + (l & 7)) * (QKS * 2) +
                                ((l >> 3) & 1) * 16 + (l >> 4) * 32);
                mma16816(ae[j], a[0], bb[0], bb[1]);
                mma16816(ae[j], a[1], bb[2], bb[3]);
            }
            // p = exp(e) directly; civ is folded into vT
            uint32_t a2[2][4];
#pragma unroll
            for (int s = 0; s < 2; s++) {
                int j0 = 2 * s, j1 = 2 * s + 1;
                a2[s][0] = bf2u(__expf(ae[j0][0]), __expf(ae[j0][1]));
                a2[s][1] = bf2u(__expf(ae[j0][2]), __expf(ae[j0][3]));
                a2[s][2] = bf2u(__expf(ae[j1][0]), __expf(ae[j1][1]));
                a2[s][3] = bf2u(__expf(ae[j1][2]), __expf(ae[j1][3]));
            }
            // PV over this 32-key half: 9 col frags per warp
#pragma unroll
            for (int j2 = 0; j2 < 9; j2++) {
                uint32_t bb[4];
                ldsm_x4(bb, vb + (72 * wc + 8 * j2 + (l & 7)) * (VSS * 2) + half * 64 +
                                ((l >> 3) & 1) * 16 + (l >> 4) * 32);
                mma16816(acc2[j2], a2[0], bb[0], bb[1]);
                mma16816(acc2[j2], a2[1], bb[2], bb[3]);
            }
        }
    }
    __syncthreads();

    if (wc == 1 && tig == 0) {            // col 128 = civ column -> denominator
        rsum[16 * wn + g] = acc2[7][0];
        rsum[16 * wn + g + 8] = acc2[7][2];
    }
    __syncthreads();

    const int row = 16 * wn + g;
    const float inv0 = 1.0f / (1e-9f + rsum[row]);
    const float inv1 = 1.0f / (1e-9f + rsum[row + 8]);
    float* dst0 = &g_xr[((size_t)b * NPTS + n0 + row) * CIN];
    float* dst1 = &g_xr[((size_t)b * NPTS + n0 + row + 8) * CIN];
#pragma unroll
    for (int j2 = 0; j2 < 9; j2++) {
        int col = 72 * wc + 8 * j2 + 2 * tig;
        if (col < 128) {
            *(float2*)&dst0[col] = make_float2(acc2[j2][0] * inv0, acc2[j2][1] * inv0);
            *(float2*)&dst1[col] = make_float2(acc2[j2][2] * inv1, acc2[j2][3] * inv1);
        }
    }
}

// ---------------- K5: y = leaky(BN((x - xr) @ Wp^T)) + x via 3-term hi/lo mma ----------------
__global__ __launch_bounds__(256) void k_proj_mma(const float* __restrict__ x,
                                                  const float* __restrict__ gamma,
                                                  const float* __restrict__ beta,
                                                  const float* __restrict__ mean,
                                                  const float* __restrict__ var,
                                                  float* __restrict__ out) {
    __shared__ __nv_bfloat16 Dh[64 * TS], Dl[64 * TS], Wh[64 * TS], Wl[64 * TS];
    const int tid = threadIdx.x, w = tid >> 5, l = tid & 31;
    const int r0 = blockIdx.x * 64;
    const int c0 = blockIdx.y * 64;
    const int wn = w & 3, wc = w >> 2;

    float acc[4][4] = {};
    for (int kc = 0; kc < CIN; kc += 64) {
        __syncthreads();
#pragma unroll
        for (int i = tid; i < 2048; i += 256) {
            int row = i >> 5, cp = i & 31;
            float2 xv = *(const float2*)&x[(size_t)(r0 + row) * CIN + kc + cp * 2];
            float2 rv = *(const float2*)&g_xr[(size_t)(r0 + row) * CIN + kc + cp * 2];
            float d0 = xv.x - rv.x, d1 = xv.y - rv.y;
            __nv_bfloat16 h0 = __float2bfloat16(d0), h1 = __float2bfloat16(d1);
            Dh[row * TS + cp * 2] = h0;
            Dh[row * TS + cp * 2 + 1] = h1;
            Dl[row * TS + cp * 2] = __float2bfloat16(d0 - __bfloat162float(h0));
            Dl[row * TS + cp * 2 + 1] = __float2bfloat16(d1 - __bfloat162float(h1));
            *(uint32_t*)&Wh[row * TS + cp * 2] = *(const uint32_t*)&g_wph[(c0 + row) * CIN + kc + cp * 2];
            *(uint32_t*)&Wl[row * TS + cp * 2] = *(const uint32_t*)&g_wpl[(c0 + row) * CIN + kc + cp * 2];
        }
        __syncthreads();
        const uint32_t dh = smem_u32(Dh), dl = smem_u32(Dl);
        const uint32_t wh = smem_u32(Wh), wl = smem_u32(Wl);
#pragma unroll
        for (int kp = 0; kp < 2; kp++) {
            uint32_t ah[2][4], al[2][4];
            ldsm_x4(ah[0], dh + (16 * wn + (l & 15)) * (TS * 2) + kp * 64 + (l >> 4) * 16);
            ldsm_x4(ah[1], dh + (16 * wn + (l & 15)) * (TS * 2) + kp * 64 + 32 + (l >> 4) * 16);
            ldsm_x4(al[0], dl + (16 * wn + (l & 15)) * (TS * 2) + kp * 64 + (l >> 4) * 16);
            ldsm_x4(al[1], dl + (16 * wn + (l & 15)) * (TS * 2) + kp * 64 + 32 + (l >> 4) * 16);
#pragma unroll
            for (int j = 0; j < 4; j++) {
                uint32_t bh[4], bl[4];
                uint32_t boff = (32 * wc + 8 * j + (l & 7)) * (TS * 2) + kp * 64 +
                                ((l >> 3) & 1) * 16 + (l >> 4) * 32;
                ldsm_x4(bh, wh + boff);
                ldsm_x4(bl, wl + boff);
                mma16816(acc[j], ah[0], bh[0], bh[1]);
                mma16816(acc[j], ah[1], bh[2], bh[3]);
                mma16816(acc[j], ah[0], bl[0], bl[1]);
                mma16816(acc[j], ah[1], bl[2], bl[3]);
                mma16816(acc[j], al[0], bh[0], bh[1]);
                mma16816(acc[j], al[1], bh[2], bh[3]);
            }
        }
    }

    const int g = l >> 2, tig = l & 3;
#pragma unroll
    for (int j = 0; j < 4; j++) {
        int o = c0 + 32 * wc + 8 * j + 2 * tig;
        float sc0 = gamma[o] * rsqrtf(var[o] + 1e-5f);
        float sc1 = gamma[o + 1] * rsqrtf(var[o + 1] + 1e-5f);
        float b0 = beta[o], b1 = beta[o + 1];
        float m0 = mean[o], m1 = mean[o + 1];
#pragma unroll
        for (int h = 0; h < 2; h++) {
            int r = r0 + 16 * wn + g + h * 8;
            float2 xv = *(const float2*)&x[(size_t)r * CIN + o];
            float y0 = (acc[j][h * 2] - m0) * sc0 + b0;
            float y1 = (acc[j][h * 2 + 1] - m1) * sc1 + b1;
            y0 = (y0 >= 0.f) ? y0 : 0.01f * y0;
            y1 = (y1 >= 0.f) ? y1 : 0.01f * y1;
            *(float2*)&out[(size_t)r * CIN + o] = make_float2(y0 + xv.x, y1 + xv.y);
        }
    }
}

// ---------------- launch ----------------
extern "C" void kernel_launch(void* const* d_in, const int* in_sizes, int n_in,
                              void* d_out, int out_size) {
    const float* x     = (const float*)d_in[0];
    const float* Wq    = (const float*)d_in[1];
    const float* Wk    = (const float*)d_in[2];
    const float* Wv    = (const float*)d_in[3];
    const float* Wp    = (const float*)d_in[4];
    const float* gamma = (const float*)d_in[5];
    const float* beta  = (const float*)d_in[6];
    const float* mean  = (const float*)d_in[7];
    const float* var   = (const float*)d_in[8];
    float* out = (float*)d_out;

    k_prep<<<(WN + BATCH * 15 * NPTS + 255) / 256, 256>>>(Wq, Wk, Wv, Wp);
    k_qkv_mma<<<dim3((BATCH * NPTS) / 64, 3), 256>>>(x);
    k_stats<<<dim3(NPTS / 128, NSEG, BATCH), 256>>>();
    k_vscale<<<dim3(8, BATCH, 8), 256>>>();
    k_xr_mma<<<dim3(NPTS / 64, BATCH), 256>>>();
    k_proj_mma<<<dim3((BATCH * NPTS) / 64, 2), 256>>>(x, gamma, beta, mean, var, out);
}

// round 15
// speedup vs baseline: 1.1346x; 1.0924x over previous
#include <cuda_runtime.h>
#include <cuda_bf16.h>
#include <cstdint>

#define BATCH 8
#define NPTS 2048
#define CIN 128
#define DQK 32
#define NSEG 8
#define VROWS 144   // 128 v channels + civ row (128) + 15 zero pad rows
#define BN (BATCH * NPTS)

// ---------------- scratch (device globals) ----------------
__device__ __nv_bfloat16 g_qh[BN * DQK];
__device__ __nv_bfloat16 g_kh[BN * DQK];
__device__ __nv_bfloat16 g_vTh[(size_t)BATCH * VROWS * NPTS];  // [b][c][m]
__device__ __nv_bfloat16 g_wh[192 * CIN], g_wl[192 * CIN];     // Wq|Wk|Wv hi/lo
__device__ __nv_bfloat16 g_wph[CIN * CIN], g_wpl[CIN * CIN];   // Wp hi/lo
__device__ float g_xr[BN * CIN];
__device__ float g_psum[BN * NSEG];

// ---------------- helpers ----------------
__device__ __forceinline__ uint32_t smem_u32(const void* p) {
    uint32_t a;
    asm("{ .reg .u64 t; cvta.to.shared.u64 t, %1; cvt.u32.u64 %0, t; }" : "=r"(a) : "l"(p));
    return a;
}
__device__ __forceinline__ void ldsm_x4(uint32_t* r, uint32_t addr) {
    asm volatile("ldmatrix.sync.aligned.m8n8.x4.shared.b16 {%0,%1,%2,%3}, [%4];"
                 : "=r"(r[0]), "=r"(r[1]), "=r"(r[2]), "=r"(r[3]) : "r"(addr));
}
__device__ __forceinline__ void mma16816(float* c, const uint32_t* a, uint32_t b0, uint32_t b1) {
    asm volatile(
        "mma.sync.aligned.m16n8k16.row.col.f32.bf16.bf16.f32 "
        "{%0,%1,%2,%3}, {%4,%5,%6,%7}, {%8,%9}, {%0,%1,%2,%3};"
        : "+f"(c[0]), "+f"(c[1]), "+f"(c[2]), "+f"(c[3])
        : "r"(a[0]), "r"(a[1]), "r"(a[2]), "r"(a[3]), "r"(b0), "r"(b1));
}
__device__ __forceinline__ uint32_t bf2u(float a, float b) {
    __nv_bfloat162 h = __nv_bfloat162(__float2bfloat16(a), __float2bfloat16(b));
    return *(uint32_t*)&h;
}
__device__ __forceinline__ void cp16(uint32_t dst, const void* src) {
    asm volatile("cp.async.cg.shared.global [%0], [%1], 16;" :: "r"(dst), "l"(src) : "memory");
}

// ---------------- K0: weights -> bf16 hi/lo, plus vT zero pad rows 129..143 ----------------
#define WN (192 * CIN + CIN * CIN)          // 40960 weight elements
__global__ __launch_bounds__(256) void k_prep(const float* __restrict__ Wq,
                                              const float* __restrict__ Wk,
                                              const float* __restrict__ Wv,
                                              const float* __restrict__ Wp) {
    int idx = blockIdx.x * 256 + threadIdx.x;
    if (idx < 192 * CIN) {
        int row = idx >> 7, col = idx & 127;
        float v;
        if (row < 32)      v = Wq[row * CIN + col];
        else if (row < 64) v = Wk[(row - 32) * CIN + col];
        else               v = Wv[(row - 64) * CIN + col];
        __nv_bfloat16 h = __float2bfloat16(v);
        g_wh[idx] = h;
        g_wl[idx] = __float2bfloat16(v - __bfloat162float(h));
    } else if (idx < WN) {
        int i2 = idx - 192 * CIN;
        float v = Wp[i2];
        __nv_bfloat16 h = __float2bfloat16(v);
        g_wph[i2] = h;
        g_wpl[i2] = __float2bfloat16(v - __bfloat162float(h));
    } else {
        int r = idx - WN;                    // over BATCH * 15 * NPTS (rows 129..143)
        int b = r / (15 * NPTS);
        int q = r - b * 15 * NPTS;
        int c = 129 + q / NPTS;
        int m = q & (NPTS - 1);
        g_vTh[((size_t)b * VROWS + c) * NPTS + m] = __float2bfloat16(0.0f);
    }
}

// ---------------- K1: q,k,v via 3-term hi/lo mma (fp32-accurate) ----------------
#define TS 72
__global__ __launch_bounds__(256) void k_qkv_mma(const float* __restrict__ x) {
    __shared__ __nv_bfloat16 Xh[64 * TS], Xl[64 * TS], Wh[64 * TS], Wl[64 * TS];
    const int tid = threadIdx.x, w = tid >> 5, l = tid & 31;
    const int r0 = blockIdx.x * 64;
    const int c0 = blockIdx.y * 64;       // [0,192): q 0-31, k 32-63, v 64-191
    const int wn = w & 3, wc = w >> 2;

    float acc[4][4] = {};
    for (int kc = 0; kc < CIN; kc += 64) {
        __syncthreads();
#pragma unroll
        for (int i = tid; i < 2048; i += 256) {
            int row = i >> 5, cp = i & 31;
            float2 v = *(const float2*)&x[(size_t)(r0 + row) * CIN + kc + cp * 2];
            __nv_bfloat16 h0 = __float2bfloat16(v.x), h1 = __float2bfloat16(v.y);
            Xh[row * TS + cp * 2] = h0;
            Xh[row * TS + cp * 2 + 1] = h1;
            Xl[row * TS + cp * 2] = __float2bfloat16(v.x - __bfloat162float(h0));
            Xl[row * TS + cp * 2 + 1] = __float2bfloat16(v.y - __bfloat162float(h1));
            *(uint32_t*)&Wh[row * TS + cp * 2] = *(const uint32_t*)&g_wh[(c0 + row) * CIN + kc + cp * 2];
            *(uint32_t*)&Wl[row * TS + cp * 2] = *(const uint32_t*)&g_wl[(c0 + row) * CIN + kc + cp * 2];
        }
        __syncthreads();
        const uint32_t xh = smem_u32(Xh), xl = smem_u32(Xl);
        const uint32_t wh = smem_u32(Wh), wl = smem_u32(Wl);
#pragma unroll
        for (int kp = 0; kp < 2; kp++) {
            uint32_t ah[2][4], al[2][4];
            ldsm_x4(ah[0], xh + (16 * wn + (l & 15)) * (TS * 2) + kp * 64 + (l >> 4) * 16);
            ldsm_x4(ah[1], xh + (16 * wn + (l & 15)) * (TS * 2) + kp * 64 + 32 + (l >> 4) * 16);
            ldsm_x4(al[0], xl + (16 * wn + (l & 15)) * (TS * 2) + kp * 64 + (l >> 4) * 16);
            ldsm_x4(al[1], xl + (16 * wn + (l & 15)) * (TS * 2) + kp * 64 + 32 + (l >> 4) * 16);
#pragma unroll
            for (int j = 0; j < 4; j++) {
                uint32_t bh[4], bl[4];
                uint32_t boff = (32 * wc + 8 * j + (l & 7)) * (TS * 2) + kp * 64 +
                                ((l >> 3) & 1) * 16 + (l >> 4) * 32;
                ldsm_x4(bh, wh + boff);
                ldsm_x4(bl, wl + boff);
                mma16816(acc[j], ah[0], bh[0], bh[1]);
                mma16816(acc[j], ah[1], bh[2], bh[3]);
                mma16816(acc[j], ah[0], bl[0], bl[1]);
                mma16816(acc[j], ah[1], bl[2], bl[3]);
                mma16816(acc[j], al[0], bh[0], bh[1]);
                mma16816(acc[j], al[1], bh[2], bh[3]);
            }
        }
    }

    const int g = l >> 2, tig = l & 3;
#pragma unroll
    for (int j = 0; j < 4; j++) {
        int col = c0 + 32 * wc + 8 * j + 2 * tig;
#pragma unroll
        for (int h = 0; h < 2; h++) {
            int r = r0 + 16 * wn + g + h * 8;
            int b = r >> 11, n = r & (NPTS - 1);
            float v0 = acc[j][h * 2], v1 = acc[j][h * 2 + 1];
            if (col < 32) {
                *(uint32_t*)&g_qh[(size_t)(b * NPTS + n) * DQK + col] = bf2u(v0, v1);
            } else if (col < 64) {
                *(uint32_t*)&g_kh[(size_t)(b * NPTS + n) * DQK + col - 32] = bf2u(v0, v1);
            } else {
                int c = col - 64;
                g_vTh[((size_t)b * VROWS + c) * NPTS + n] = __float2bfloat16(v0);
                g_vTh[((size_t)b * VROWS + c + 1) * NPTS + n] = __float2bfloat16(v1);
            }
        }
    }
}

// ---------------- K2: column sums of exp(E) via transposed E ----------------
#define QKS 40
__global__ __launch_bounds__(256) void k_stats() {
    __shared__ __nv_bfloat16 Ks[128 * QKS];
    __shared__ __nv_bfloat16 Qs[128 * QKS];
    const int tid = threadIdx.x, w = tid >> 5, l = tid & 31;
    const int b = blockIdx.z, m0 = blockIdx.x * 128, seg = blockIdx.y;

#pragma unroll
    for (int i = tid; i < 512; i += 256) {
        int row = i >> 2, jj = i & 3;
        *(uint4*)&Ks[row * QKS + jj * 8] =
            *(const uint4*)&g_kh[(size_t)(b * NPTS + m0 + row) * DQK + jj * 8];
    }
    __syncthreads();

    const uint32_t kb = smem_u32(Ks), qb = smem_u32(Qs);
    uint32_t a[2][4];       // K fragments (constant across q-tiles)
    ldsm_x4(a[0], kb + (16 * w + (l & 15)) * (QKS * 2) + (l >> 4) * 16);
    ldsm_x4(a[1], kb + (16 * w + (l & 15)) * (QKS * 2) + 32 + (l >> 4) * 16);

    float sum0 = 0.f, sum1 = 0.f;
#pragma unroll
    for (int t = 0; t < 2; t++) {
        const int q0 = (seg * 2 + t) * 128;
        __syncthreads();
#pragma unroll
        for (int i = tid; i < 512; i += 256) {
            int row = i >> 2, jj = i & 3;
            *(uint4*)&Qs[row * QKS + jj * 8] =
                *(const uint4*)&g_qh[(size_t)(b * NPTS + q0 + row) * DQK + jj * 8];
        }
        __syncthreads();
#pragma unroll
        for (int j = 0; j < 16; j++) {
            float acc[4] = {0.f, 0.f, 0.f, 0.f};
            uint32_t bb[4];
            ldsm_x4(bb, qb + (8 * j + (l & 7)) * (QKS * 2) + ((l >> 3) & 1) * 16 + (l >> 4) * 32);
            mma16816(acc, a[0], bb[0], bb[1]);
            mma16816(acc, a[1], bb[2], bb[3]);
            sum0 += __expf(acc[0]) + __expf(acc[1]);
            sum1 += __expf(acc[2]) + __expf(acc[3]);
        }
    }

    sum0 += __shfl_xor_sync(0xFFFFFFFFu, sum0, 1);
    sum0 += __shfl_xor_sync(0xFFFFFFFFu, sum0, 2);
    sum1 += __shfl_xor_sync(0xFFFFFFFFu, sum1, 1);
    sum1 += __shfl_xor_sync(0xFFFFFFFFu, sum1, 2);
    if ((l & 3) == 0) {
        int m = m0 + 16 * w + (l >> 2);
        g_psum[(b * NPTS + m) * NSEG + seg] = sum0;
        g_psum[(b * NPTS + m + 8) * NSEG + seg] = sum1;
    }
}

// ---------------- K3: fused civ + vT pre-scale, parallel over 8 row-groups ----------------
__global__ __launch_bounds__(256) void k_vscale() {
    __shared__ float civ[256];
    const int tid = threadIdx.x;
    const int m0 = blockIdx.x * 256;
    const int b = blockIdx.y;
    const int rg = blockIdx.z;

    {   // stage 1: civ[m] = 1 / sum(psum[m][0..7])
        const float* ps = &g_psum[(size_t)(b * NPTS + m0 + tid) * NSEG];
        float s = ps[0] + ps[1] + ps[2] + ps[3] + ps[4] + ps[5] + ps[6] + ps[7];
        civ[tid] = 1.0f / s;
    }
    __syncthreads();

    const int nrows = (rg == 7) ? 17 : 16;
#pragma unroll 2
    for (int i = tid; i < nrows * 32; i += 256) {
        int cr = i >> 5;
        int c = (cr == 16) ? 128 : (rg * 16 + cr);
        int m8 = (i & 31) * 8;
        __nv_bfloat16* dst = &g_vTh[((size_t)b * VROWS + c) * NPTS + m0 + m8];
        uint4 out;
        __nv_bfloat16* o = (__nv_bfloat16*)&out;
        if (c < 128) {
            uint4 raw = *(uint4*)dst;
            __nv_bfloat16* v = (__nv_bfloat16*)&raw;
#pragma unroll
            for (int k = 0; k < 8; k++)
                o[k] = __float2bfloat16(__bfloat162float(v[k]) * civ[m8 + k]);
        } else {
#pragma unroll
            for (int k = 0; k < 8; k++) o[k] = __float2bfloat16(civ[m8 + k]);
        }
        *(uint4*)dst = out;
    }
}

// ---------------- K4: x_r — cp.async double-buffered K/V pipeline ----------------
// Block: 64 query rows; 8 warps = 4 row-groups x 2 col-halves (72 cols each).
// Dynamic smem: Qs (2560) | Kc[2] (2x2560) | Vts[2] (2x10368) bf16 = 56832 B.
#define VSS 72
#define KC_ELEMS (64 * QKS)
#define VT_ELEMS (VROWS * VSS)
#define XR_SMEM ((64 * QKS + 2 * KC_ELEMS + 2 * VT_ELEMS) * 2)
__global__ __launch_bounds__(256, 2) void k_xr_mma() {
    extern __shared__ __nv_bfloat16 dyn[];
    __nv_bfloat16* Qs = dyn;
    __nv_bfloat16* Kc = Qs + 64 * QKS;          // [2][KC_ELEMS]
    __nv_bfloat16* Vt = Kc + 2 * KC_ELEMS;      // [2][VT_ELEMS]
    __shared__ float rsum[64];
    const int tid = threadIdx.x, w = tid >> 5, l = tid & 31;
    const int b = blockIdx.y, n0 = blockIdx.x * 64;
    const int g = l >> 2, tig = l & 3;
    const int wn = w & 3, wc = w >> 2;

    {
        int row = tid >> 2, jj = tid & 3;   // exactly 256 uint4
        *(uint4*)&Qs[row * QKS + jj * 8] =
            *(const uint4*)&g_qh[(size_t)(b * NPTS + n0 + row) * DQK + jj * 8];
    }
    const uint32_t qb = smem_u32(Qs), kb = smem_u32(Kc), vb = smem_u32(Vt);

    // issue cp.async for chunk ci into buffer s
    auto issue_chunk = [&](int ci, int s) {
        const int mc = ci * 64;
        {
            int row = tid >> 2, jj = tid & 3;   // 256 uint4 (K tile)
            cp16(kb + (uint32_t)(s * KC_ELEMS + row * QKS + jj * 8) * 2,
                 &g_kh[(size_t)(b * NPTS + mc + row) * DQK + jj * 8]);
        }
#pragma unroll
        for (int i = tid; i < 1152; i += 256) { // 1152 uint4 (V tile)
            int row = i >> 3, jj = i & 7;
            cp16(vb + (uint32_t)(s * VT_ELEMS + row * VSS + jj * 8) * 2,
                 &g_vTh[((size_t)b * VROWS + row) * NPTS + mc + jj * 8]);
        }
        asm volatile("cp.async.commit_group;" ::: "memory");
    };

    float acc2[9][4];
#pragma unroll
    for (int j = 0; j < 9; j++)
#pragma unroll
        for (int q = 0; q < 4; q++) acc2[j][q] = 0.f;

    issue_chunk(0, 0);
    issue_chunk(1, 1);

    __syncthreads();    // Qs visible
    uint32_t a[2][4];   // Q fragments constant across chunks
    ldsm_x4(a[0], qb + (16 * wn + (l & 15)) * (QKS * 2) + (l >> 4) * 16);
    ldsm_x4(a[1], qb + (16 * wn + (l & 15)) * (QKS * 2) + 32 + (l >> 4) * 16);

    for (int ci = 0; ci < 32; ci++) {
        const int s = ci & 1;
        asm volatile("cp.async.wait_group 1;" ::: "memory");
        __syncthreads();

        const uint32_t kbs = kb + (uint32_t)(s * KC_ELEMS) * 2;
        const uint32_t vbs = vb + (uint32_t)(s * VT_ELEMS) * 2;

#pragma unroll
        for (int half = 0; half < 2; half++) {
            // E for keys [64*ci + 32*half, +32): 4 frags
            float ae[4][4];
#pragma unroll
            for (int j = 0; j < 4; j++)
#pragma unroll
                for (int q = 0; q < 4; q++) ae[j][q] = 0.f;
#pragma unroll
            for (int j = 0; j < 4; j++) {
                uint32_t bb[4];
                ldsm_x4(bb, kbs + (8 * (4 * half + j) + (l & 7)) * (QKS * 2) +
                                 ((l >> 3) & 1) * 16 + (l >> 4) * 32);
                mma16816(ae[j], a[0], bb[0], bb[1]);
                mma16816(ae[j], a[1], bb[2], bb[3]);
            }
            // p = exp(e) directly; civ is folded into vT
            uint32_t a2[2][4];
#pragma unroll
            for (int s2 = 0; s2 < 2; s2++) {
                int j0 = 2 * s2, j1 = 2 * s2 + 1;
                a2[s2][0] = bf2u(__expf(ae[j0][0]), __expf(ae[j0][1]));
                a2[s2][1] = bf2u(__expf(ae[j0][2]), __expf(ae[j0][3]));
                a2[s2][2] = bf2u(__expf(ae[j1][0]), __expf(ae[j1][1]));
                a2[s2][3] = bf2u(__expf(ae[j1][2]), __expf(ae[j1][3]));
            }
            // PV over this 32-key half: 9 col frags per warp
#pragma unroll
            for (int j2 = 0; j2 < 9; j2++) {
                uint32_t bb[4];
                ldsm_x4(bb, vbs + (72 * wc + 8 * j2 + (l & 7)) * (VSS * 2) + half * 64 +
                                  ((l >> 3) & 1) * 16 + (l >> 4) * 32);
                mma16816(acc2[j2], a2[0], bb[0], bb[1]);
                mma16816(acc2[j2], a2[1], bb[2], bb[3]);
            }
        }
        __syncthreads();                  // all warps done reading buffer s
        if (ci + 2 < 32) issue_chunk(ci + 2, s);
    }
    __syncthreads();

    if (wc == 1 && tig == 0) {            // col 128 = civ column -> denominator
        rsum[16 * wn + g] = acc2[7][0];
        rsum[16 * wn + g + 8] = acc2[7][2];
    }
    __syncthreads();

    const int row = 16 * wn + g;
    const float inv0 = 1.0f / (1e-9f + rsum[row]);
    const float inv1 = 1.0f / (1e-9f + rsum[row + 8]);
    float* dst0 = &g_xr[((size_t)b * NPTS + n0 + row) * CIN];
    float* dst1 = &g_xr[((size_t)b * NPTS + n0 + row + 8) * CIN];
#pragma unroll
    for (int j2 = 0; j2 < 9; j2++) {
        int col = 72 * wc + 8 * j2 + 2 * tig;
        if (col < 128) {
            *(float2*)&dst0[col] = make_float2(acc2[j2][0] * inv0, acc2[j2][1] * inv0);
            *(float2*)&dst1[col] = make_float2(acc2[j2][2] * inv1, acc2[j2][3] * inv1);
        }
    }
}

// ---------------- K5: y = leaky(BN((x - xr) @ Wp^T)) + x via 3-term hi/lo mma ----------------
__global__ __launch_bounds__(256) void k_proj_mma(const float* __restrict__ x,
                                                  const float* __restrict__ gamma,
                                                  const float* __restrict__ beta,
                                                  const float* __restrict__ mean,
                                                  const float* __restrict__ var,
                                                  float* __restrict__ out) {
    __shared__ __nv_bfloat16 Dh[64 * TS], Dl[64 * TS], Wh[64 * TS], Wl[64 * TS];
    const int tid = threadIdx.x, w = tid >> 5, l = tid & 31;
    const int r0 = blockIdx.x * 64;
    const int c0 = blockIdx.y * 64;
    const int wn = w & 3, wc = w >> 2;

    float acc[4][4] = {};
    for (int kc = 0; kc < CIN; kc += 64) {
        __syncthreads();
#pragma unroll
        for (int i = tid; i < 2048; i += 256) {
            int row = i >> 5, cp = i & 31;
            float2 xv = *(const float2*)&x[(size_t)(r0 + row) * CIN + kc + cp * 2];
            float2 rv = *(const float2*)&g_xr[(size_t)(r0 + row) * CIN + kc + cp * 2];
            float d0 = xv.x - rv.x, d1 = xv.y - rv.y;
            __nv_bfloat16 h0 = __float2bfloat16(d0), h1 = __float2bfloat16(d1);
            Dh[row * TS + cp * 2] = h0;
            Dh[row * TS + cp * 2 + 1] = h1;
            Dl[row * TS + cp * 2] = __float2bfloat16(d0 - __bfloat162float(h0));
            Dl[row * TS + cp * 2 + 1] = __float2bfloat16(d1 - __bfloat162float(h1));
            *(uint32_t*)&Wh[row * TS + cp * 2] = *(const uint32_t*)&g_wph[(c0 + row) * CIN + kc + cp * 2];
            *(uint32_t*)&Wl[row * TS + cp * 2] = *(const uint32_t*)&g_wpl[(c0 + row) * CIN + kc + cp * 2];
        }
        __syncthreads();
        const uint32_t dh = smem_u32(Dh), dl = smem_u32(Dl);
        const uint32_t wh = smem_u32(Wh), wl = smem_u32(Wl);
#pragma unroll
        for (int kp = 0; kp < 2; kp++) {
            uint32_t ah[2][4], al[2][4];
            ldsm_x4(ah[0], dh + (16 * wn + (l & 15)) * (TS * 2) + kp * 64 + (l >> 4) * 16);
            ldsm_x4(ah[1], dh + (16 * wn + (l & 15)) * (TS * 2) + kp * 64 + 32 + (l >> 4) * 16);
            ldsm_x4(al[0], dl + (16 * wn + (l & 15)) * (TS * 2) + kp * 64 + (l >> 4) * 16);
            ldsm_x4(al[1], dl + (16 * wn + (l & 15)) * (TS * 2) + kp * 64 + 32 + (l >> 4) * 16);
#pragma unroll
            for (int j = 0; j < 4; j++) {
                uint32_t bh[4], bl[4];
                uint32_t boff = (32 * wc + 8 * j + (l & 7)) * (TS * 2) + kp * 64 +
                                ((l >> 3) & 1) * 16 + (l >> 4) * 32;
                ldsm_x4(bh, wh + boff);
                ldsm_x4(bl, wl + boff);
                mma16816(acc[j], ah[0], bh[0], bh[1]);
                mma16816(acc[j], ah[1], bh[2], bh[3]);
                mma16816(acc[j], ah[0], bl[0], bl[1]);
                mma16816(acc[j], ah[1], bl[2], bl[3]);
                mma16816(acc[j], al[0], bh[0], bh[1]);
                mma16816(acc[j], al[1], bh[2], bh[3]);
            }
        }
    }

    const int g = l >> 2, tig = l & 3;
#pragma unroll
    for (int j = 0; j < 4; j++) {
        int o = c0 + 32 * wc + 8 * j + 2 * tig;
        float sc0 = gamma[o] * rsqrtf(var[o] + 1e-5f);
        float sc1 = gamma[o + 1] * rsqrtf(var[o + 1] + 1e-5f);
        float b0 = beta[o], b1 = beta[o + 1];
        float m0 = mean[o], m1 = mean[o + 1];
#pragma unroll
        for (int h = 0; h < 2; h++) {
            int r = r0 + 16 * wn + g + h * 8;
            float2 xv = *(const float2*)&x[(size_t)r * CIN + o];
            float y0 = (acc[j][h * 2] - m0) * sc0 + b0;
            float y1 = (acc[j][h * 2 + 1] - m1) * sc1 + b1;
            y0 = (y0 >= 0.f) ? y0 : 0.01f * y0;
            y1 = (y1 >= 0.f) ? y1 : 0.01f * y1;
            *(float2*)&out[(size_t)r * CIN + o] = make_float2(y0 + xv.x, y1 + xv.y);
        }
    }
}

// ---------------- launch ----------------
extern "C" void kernel_launch(void* const* d_in, const int* in_sizes, int n_in,
                              void* d_out, int out_size) {
    const float* x     = (const float*)d_in[0];
    const float* Wq    = (const float*)d_in[1];
    const float* Wk    = (const float*)d_in[2];
    const float* Wv    = (const float*)d_in[3];
    const float* Wp    = (const float*)d_in[4];
    const float* gamma = (const float*)d_in[5];
    const float* beta  = (const float*)d_in[6];
    const float* mean  = (const float*)d_in[7];
    const float* var   = (const float*)d_in[8];
    float* out = (float*)d_out;

    cudaFuncSetAttribute(k_xr_mma, cudaFuncAttributeMaxDynamicSharedMemorySize, XR_SMEM);

    k_prep<<<(WN + BATCH * 15 * NPTS + 255) / 256, 256>>>(Wq, Wk, Wv, Wp);
    k_qkv_mma<<<dim3((BATCH * NPTS) / 64, 3), 256>>>(x);
    k_stats<<<dim3(NPTS / 128, NSEG, BATCH), 256>>>();
    k_vscale<<<dim3(8, BATCH, 8), 256>>>();
    k_xr_mma<<<dim3(NPTS / 64, BATCH), 256, XR_SMEM>>>();
    k_proj_mma<<<dim3((BATCH * NPTS) / 64, 2), 256>>>(x, gamma, beta, mean, var, out);
}